// round 13
// baseline (speedup 1.0000x reference)
#include <cuda_runtime.h>
#include <math.h>

#define BATCH 32
#define REPD  1024
#define NV    504
#define NR    190
#define NN    11538
#define MR    6
#define HID   32
#define NH    4
#define HD    8
#define MAXN  512
#define LBH   (NR*BATCH*HID)

#define OFF_REP     0
#define OFF_VPOT    32768
#define OFF_RN      48896
#define OFF_NORM    70199936
#define OFF_VMAX    70199968
#define OFF_VRMAXI  70216096

__device__ float g_buf[2][LBH];
__device__ float g_marg[(NR+1)*BATCH];
__device__ float g_rmax[(NR+1)*BATCH];
__device__ int   g_rmaxi[(NR+1)*BATCH];
__device__ float g_wn[(size_t)HID*NN];     // fused Wn' [32][NN]
__device__ float g_wnT[(size_t)NN*HID];    // fused Wn' transposed [NN][32]
__device__ float g_bn[NN];                 // fused bn'
__device__ float g_iw[2*96*HID];           // fused in_w for layers 1,2
__device__ float g_ib[2*96];

__device__ __forceinline__ unsigned long long pack2dup(float x) {
    unsigned long long r;
    asm("mov.b64 %0, {%1, %1};" : "=l"(r) : "f"(x));
    return r;
}
__device__ __forceinline__ unsigned long long pack2(float x, float y) {
    unsigned long long r;
    asm("mov.b64 %0, {%1, %2};" : "=l"(r) : "f"(x), "f"(y));
    return r;
}
__device__ __forceinline__ void ffma2(unsigned long long &c, unsigned long long a, unsigned long long b) {
    asm("fma.rn.f32x2 %0, %1, %2, %0;" : "+l"(c) : "l"(a), "l"(b));
}
__device__ __forceinline__ float2 unpack2(unsigned long long v) {
    float2 f;
    asm("mov.b64 {%0, %1}, %2;" : "=f"(f.x), "=f"(f.y) : "l"(v));
    return f;
}

// =====================================================================
// launch 1 (k_front), 300 blocks x 256, 21.1KB smem union:
//   bid 0..45   : fuse Wn' = ow2^T@Wn, bn' = bn + ob2@Wn
//   bid 46..108 : v_potential (KC=128 tiles)
//   bid 109..298: node0 = rep @ W_r + b_r
//   bid 299     : fuse in_w/in_b for layers 1,2
// =====================================================================
__global__ __launch_bounds__(256) void k_front(
        const float* __restrict__ rep, const float* __restrict__ Wv,
        const float* __restrict__ bv, const float* __restrict__ Wr,
        const float* __restrict__ br, const float* __restrict__ aiw,
        const float* __restrict__ aib, const float* __restrict__ aow,
        const float* __restrict__ aob, const float* __restrict__ Wn,
        const float* __restrict__ bn, float* __restrict__ out_vpot) {
    __shared__ __align__(16) float S[5280];
    int tid = threadIdx.x;
    int bid = blockIdx.x;
    if (bid < 46) {
        float (*ows)[32] = reinterpret_cast<float(*)[32]>(S);   // [32][32]
        float *obs = S + 1024;
        for (int e = tid; e < 1024; e += 256) ows[e>>5][e&31] = aow[2*1024 + e];
        if (tid < 32) obs[tid] = aob[2*32 + tid];
        __syncthreads();
        int n = bid*256 + tid;
        if (n < NN) {
            float col[32];
            #pragma unroll
            for (int e = 0; e < 32; e++) col[e] = Wn[(size_t)e*NN + n];
            float wrow[32];
            #pragma unroll 4
            for (int f = 0; f < 32; f++) {
                float a = 0.f;
                #pragma unroll
                for (int e = 0; e < 32; e++) a = fmaf(ows[e][f], col[e], a);
                wrow[f] = a;
            }
            #pragma unroll
            for (int f = 0; f < 32; f++) {
                g_wn[(size_t)f*NN + n] = wrow[f];
                g_wnT[(size_t)n*32 + f] = wrow[f];
            }
            float bacc = bn[n];
            #pragma unroll
            for (int e = 0; e < 32; e++) bacc = fmaf(obs[e], col[e], bacc);
            g_bn[n] = bacc;
        }
        return;
    }
    if (bid < 109) {
        float (*rs)[132]  = reinterpret_cast<float(*)[132]>(S);          // [32][132]
        float (*wvT)[132] = reinterpret_cast<float(*)[132]>(S + 4224);   // [8][132]
        int vb = (bid - 46)*8;
        int b = tid >> 3, j = tid & 7;
        float acc = bv[vb + j];
        for (int kc = 0; kc < REPD; kc += 128) {
            for (int e = tid; e < 32*128; e += 256) {
                int bi = e >> 7, kk = e & 127;
                rs[bi][kk] = rep[bi*REPD + kc + kk];
            }
            for (int e = tid; e < 1024; e += 256) {
                int kk = e >> 3, jj = e & 7;
                wvT[jj][kk] = Wv[(size_t)(kc+kk)*NV + vb + jj];
            }
            __syncthreads();
            #pragma unroll 8
            for (int kk = 0; kk < 128; kk += 4) {
                float4 r4 = *reinterpret_cast<const float4*>(&rs[b][kk]);
                float4 w4 = *reinterpret_cast<const float4*>(&wvT[j][kk]);
                acc = fmaf(r4.x, w4.x, acc); acc = fmaf(r4.y, w4.y, acc);
                acc = fmaf(r4.z, w4.z, acc); acc = fmaf(r4.w, w4.w, acc);
            }
            __syncthreads();
        }
        out_vpot[b*NV + vb + j] = acc;
        return;
    }
    if (bid == 299) {
        float (*owp)[32][32] = reinterpret_cast<float(*)[32][32]>(S);     // [2][32][32]
        float (*obp)[32]     = reinterpret_cast<float(*)[32]>(S + 2048);  // [2][32]
        float (*aiws)[32]    = reinterpret_cast<float(*)[32]>(S + 2112);  // [96][32]
        for (int e = tid; e < 2048; e += 256) owp[e>>10][(e>>5)&31][e&31] = aow[e];
        if (tid < 64) obp[tid>>5][tid&31] = aob[tid];
        for (int jj = 0; jj < 2; jj++) {
            __syncthreads();
            for (int e = tid; e < 3072; e += 256) aiws[e>>5][e&31] = aiw[(jj+1)*3072 + e];
            __syncthreads();
            for (int t = tid; t < 3072; t += 256) {
                int r = t >> 5, f = t & 31;
                float a = 0.f;
                #pragma unroll
                for (int e = 0; e < 32; e++) a = fmaf(aiws[r][e], owp[jj][e][f], a);
                g_iw[jj*3072 + r*32 + f] = a;
            }
            if (tid < 96) {
                float a = aib[(jj+1)*96 + tid];
                #pragma unroll
                for (int e = 0; e < 32; e++) a = fmaf(aiws[tid][e], obp[jj][e], a);
                g_ib[jj*96 + tid] = a;
            }
        }
        return;
    }
    const int l = bid - 109;
    float (*rs2)[65] = reinterpret_cast<float(*)[65]>(S);          // [32][65]
    float (*ws2)[32] = reinterpret_cast<float(*)[32]>(S + 2080);   // [64][32]
    int bb = tid >> 3, hq = tid & 7;
    float c0 = 0.f, c1 = 0.f, c2 = 0.f, c3 = 0.f;
    for (int k0 = 0; k0 < REPD; k0 += 64) {
        for (int e = tid; e < 32*64; e += 256) {
            int bi = e >> 6, kk = e & 63;
            rs2[bi][kk] = rep[bi*REPD + k0 + kk];
        }
        for (int e = tid; e < 64*32; e += 256) {
            int kk = e >> 5, hh = e & 31;
            ws2[kk][hh] = Wr[(size_t)(k0+kk)*(NR*HID) + l*HID + hh];
        }
        __syncthreads();
        #pragma unroll 8
        for (int kk = 0; kk < 64; kk++) {
            float a = rs2[bb][kk];
            float4 w4 = *reinterpret_cast<const float4*>(&ws2[kk][hq*4]);
            c0 = fmaf(a, w4.x, c0); c1 = fmaf(a, w4.y, c1);
            c2 = fmaf(a, w4.z, c2); c3 = fmaf(a, w4.w, c3);
        }
        __syncthreads();
    }
    float* o = &g_buf[0][l*(BATCH*HID) + bb*HID];
    const float* bb_ = br + l*HID;
    o[hq*4+0] = c0 + bb_[hq*4+0];
    o[hq*4+1] = c1 + bb_[hq*4+1];
    o[hq*4+2] = c2 + bb_[hq*4+2];
    o[hq*4+3] = c3 + bb_[hq*4+3];
}

// =====================================================================
// attention per (b,h): 768 threads, 4 threads per query row (key-split),
// branchless two-pass softmax with smem partial merges
// =====================================================================
__global__ __launch_bounds__(768) void k_attn(const float* __restrict__ aiw,
                                              const float* __restrict__ aib,
                                              int layer, int src, int dst) {
    __shared__ __align__(16) float S[11840];
    float (*xs)[33]  = reinterpret_cast<float(*)[33]>(S);          // [190][33]
    float (*qs)[9]   = reinterpret_cast<float(*)[9]>(S + 6272);    // [190][9]
    float (*ks)[8]   = reinterpret_cast<float(*)[8]>(S + 7984);    // [190][8]
    float (*vs)[8]   = reinterpret_cast<float(*)[8]>(S + 9504);    // [190][8]
    float (*wsm)[32] = reinterpret_cast<float(*)[32]>(S + 11024);  // [24][32]
    float *bs        = S + 11792;                                   // [24]
    float *pmax      = S;                                           // [4*192]
    float *psum      = S + 768;                                     // [4*192]
    float (*po)[8]   = reinterpret_cast<float(*)[8]>(S + 1536);     // [4*192][8]

    int b = blockIdx.x, h = blockIdx.y;
    const float* w  = (layer == 0) ? aiw : (g_iw + (layer-1)*3072);
    const float* bi = (layer == 0) ? aib : (g_ib + (layer-1)*96);
    const float* x = &g_buf[src][0];
    int tid = threadIdx.x;            // 768
    int p = tid / 192;                // key-quarter 0..3
    int l = tid - p*192;              // query row 0..191

    for (int e = tid; e < NR*HID; e += 768) {
        int ll = e >> 5, c = e & 31;
        xs[ll][c] = x[ll*(BATCH*HID) + b*HID + c];
    }
    {
        int r = tid >> 5, c = tid & 31;
        if (r < 24) {
            int row = (r >> 3)*32 + h*8 + (r & 7);
            wsm[r][c] = w[row*HID + c];
        }
    }
    if (tid < 24) {
        int row = (tid >> 3)*32 + h*8 + (tid & 7);
        bs[tid] = bi[row];
    }
    __syncthreads();

    const float scale = 0.35355339059327373f;
    if (l < NR) {
        float xr[HID];
        #pragma unroll
        for (int e = 0; e < HID; e++) xr[e] = xs[l][e];
        #pragma unroll
        for (int rr = 0; rr < 6; rr++) {
            int r = p*6 + rr;
            float a = bs[r];
            #pragma unroll
            for (int e = 0; e < HID; e++) a = fmaf(xr[e], wsm[r][e], a);
            if (r < 8)       qs[l][r]    = a * scale;
            else if (r < 16) ks[l][r-8]  = a;
            else             vs[l][r-16] = a;
        }
    }
    __syncthreads();

    int m0 = p*48;
    int mend = (m0 + 48 < NR) ? (m0 + 48) : NR;
    float q[HD];
    float mx = -INFINITY;
    if (l < NR) {
        #pragma unroll
        for (int d = 0; d < HD; d++) q[d] = qs[l][d];
        #pragma unroll 4
        for (int m = m0; m < mend; m++) {
            const float4* k4 = reinterpret_cast<const float4*>(&ks[m][0]);
            float4 ka = k4[0], kb = k4[1];
            float sa = q[0]*ka.x + q[1]*ka.y;
            float sb = q[2]*ka.z + q[3]*ka.w;
            float sc = q[4]*kb.x + q[5]*kb.y;
            float sd = q[6]*kb.z + q[7]*kb.w;
            mx = fmaxf(mx, (sa+sb)+(sc+sd));
        }
        pmax[p*192 + l] = mx;
    }
    __syncthreads();

    float sum = 0.f;
    float o[HD] = {0,0,0,0,0,0,0,0};
    if (l < NR) {
        float gm = fmaxf(fmaxf(pmax[l], pmax[192+l]), fmaxf(pmax[384+l], pmax[576+l]));
        #pragma unroll 4
        for (int m = m0; m < mend; m++) {
            const float4* k4 = reinterpret_cast<const float4*>(&ks[m][0]);
            float4 ka = k4[0], kb = k4[1];
            float sa = q[0]*ka.x + q[1]*ka.y;
            float sb = q[2]*ka.z + q[3]*ka.w;
            float sc = q[4]*kb.x + q[5]*kb.y;
            float sd = q[6]*kb.z + q[7]*kb.w;
            float pe = __expf((sa+sb)+(sc+sd) - gm);
            sum += pe;
            const float4* v4 = reinterpret_cast<const float4*>(&vs[m][0]);
            float4 va = v4[0], vb4 = v4[1];
            o[0] = fmaf(pe, va.x, o[0]);  o[1] = fmaf(pe, va.y, o[1]);
            o[2] = fmaf(pe, va.z, o[2]);  o[3] = fmaf(pe, va.w, o[3]);
            o[4] = fmaf(pe, vb4.x, o[4]); o[5] = fmaf(pe, vb4.y, o[5]);
            o[6] = fmaf(pe, vb4.z, o[6]); o[7] = fmaf(pe, vb4.w, o[7]);
        }
        psum[p*192 + l] = sum;
        #pragma unroll
        for (int d = 0; d < HD; d++) po[p*192 + l][d] = o[d];
    }
    __syncthreads();

    // tail merge parallelized over all four p-groups: each handles 2 of 8 dims
    if (l < NR) {
        float st = psum[l] + psum[192+l] + psum[384+l] + psum[576+l];
        float inv = 1.0f / st;
        float* dp = &g_buf[dst][l*(BATCH*HID) + b*HID + h*HD];
        #pragma unroll
        for (int dd = 0; dd < 2; dd++) {
            int d = p*2 + dd;
            dp[d] = (po[l][d] + po[192+l][d] + po[384+l][d] + po[576+l][d]) * inv;
        }
    }
}

// ---- rn = ctx2 @ Wn' + bn'  (M=6080, N=11538, K=32), FFMA2 (R10 form) ----
__global__ __launch_bounds__(256) void k_rngemm(float* __restrict__ out) {
    const int m0 = blockIdx.y * 64;
    const int n0 = blockIdx.x * 256;
    __shared__ __align__(16) float aT[32][68];
    __shared__ __align__(16) float wsm[32][256];
    const float* A = &g_buf[1][0];
    int tid = threadIdx.x, tx = tid & 31, ty = tid >> 5;
    for (int e = tid; e < 64*32; e += 256) {
        int m = e >> 5, k = e & 31;
        aT[k][m] = A[(m0+m)*32 + k];
    }
    for (int e = tid; e < 32*256; e += 256) {
        int k = e >> 8, n = e & 255;
        int gn = n0 + n;
        wsm[k][n] = (gn < NN) ? g_wn[(size_t)k*NN + gn] : 0.0f;
    }
    __syncthreads();

    unsigned long long c[8][4];
    #pragma unroll
    for (int q = 0; q < 4; q++) {
        int gn = n0 + 2*tx + 64*q;
        float b0 = (gn   < NN) ? g_bn[gn]   : 0.f;
        float b1 = (gn+1 < NN) ? g_bn[gn+1] : 0.f;
        unsigned long long bp = pack2(b0, b1);
        #pragma unroll
        for (int i = 0; i < 8; i++) c[i][q] = bp;
    }
    const int mb = ty*8;
    #pragma unroll 8
    for (int k = 0; k < 32; k++) {
        float4 a0 = *reinterpret_cast<const float4*>(&aT[k][mb]);
        float4 a1 = *reinterpret_cast<const float4*>(&aT[k][mb+4]);
        unsigned long long Aa[8];
        Aa[0] = pack2dup(a0.x); Aa[1] = pack2dup(a0.y);
        Aa[2] = pack2dup(a0.z); Aa[3] = pack2dup(a0.w);
        Aa[4] = pack2dup(a1.x); Aa[5] = pack2dup(a1.y);
        Aa[6] = pack2dup(a1.z); Aa[7] = pack2dup(a1.w);
        unsigned long long Bb[4];
        Bb[0] = *reinterpret_cast<const unsigned long long*>(&wsm[k][2*tx]);
        Bb[1] = *reinterpret_cast<const unsigned long long*>(&wsm[k][2*tx+64]);
        Bb[2] = *reinterpret_cast<const unsigned long long*>(&wsm[k][2*tx+128]);
        Bb[3] = *reinterpret_cast<const unsigned long long*>(&wsm[k][2*tx+192]);
        #pragma unroll
        for (int i = 0; i < 8; i++) {
            #pragma unroll
            for (int q = 0; q < 4; q++) ffma2(c[i][q], Aa[i], Bb[q]);
        }
    }
    #pragma unroll
    for (int i = 0; i < 8; i++) {
        size_t row = (size_t)(m0 + mb + i) * NN;
        #pragma unroll
        for (int q = 0; q < 4; q++) {
            int gn = n0 + 2*tx + 64*q;
            float2 pv = unpack2(c[i][q]);
            if (gn + 1 < NN)  __stcs(reinterpret_cast<float2*>(&out[row + gn]), pv);
            else if (gn < NN) __stcs(&out[row + gn], pv.x);
        }
    }
}

// ---- per-role: recompute gathered logits from L2-resident WnT ----
__global__ void k_roles(const int* __restrict__ rnidx) {
    int r = blockIdx.x;
    __shared__ int idx_s[MAXN];
    __shared__ float node_s[32][33];
    __shared__ float colsm[256][33];
    __shared__ float bns[256];
    int tid = threadIdx.x;  // 256
    for (int e = tid; e < MAXN; e += 256) idx_s[e] = rnidx[r*MAXN + e];
    for (int e = tid; e < 1024; e += 256) node_s[e>>5][e&31] = g_buf[1][r*(BATCH*HID) + e];
    if (r == 0 && tid < BATCH) { g_marg[tid] = 0.f; g_rmax[tid] = 0.f; g_rmaxi[tid] = 0; }
    int w = tid >> 5, lane = tid & 31;
    float m_[4], s_[4], bv_[4];
    int bj_[4];
    #pragma unroll
    for (int i = 0; i < 4; i++) { m_[i] = -INFINITY; s_[i] = 0.f; bv_[i] = -INFINITY; bj_[i] = 0; }
    for (int pass = 0; pass < 2; pass++) {
        __syncthreads();
        for (int e = tid; e < 256*8; e += 256) {
            int jl = e >> 3, q = e & 7;
            const float4* srcp = reinterpret_cast<const float4*>(g_wnT + (size_t)idx_s[pass*256 + jl]*32);
            float4 v = srcp[q];
            colsm[jl][q*4+0] = v.x; colsm[jl][q*4+1] = v.y;
            colsm[jl][q*4+2] = v.z; colsm[jl][q*4+3] = v.w;
        }
        bns[tid] = g_bn[idx_s[pass*256 + tid]];
        __syncthreads();
        #pragma unroll
        for (int bi = 0; bi < 4; bi++) {
            int b = w + 8*bi;
            float nb[32];
            #pragma unroll
            for (int k = 0; k < 32; k++) nb[k] = node_s[b][k];
            for (int q = 0; q < 8; q++) {
                int jl = q*32 + lane;
                float val = bns[jl];
                #pragma unroll
                for (int k = 0; k < 32; k++) val = fmaf(nb[k], colsm[jl][k], val);
                if (val > m_[bi]) { s_[bi] = s_[bi]*__expf(m_[bi] - val) + 1.f; m_[bi] = val; }
                else              { s_[bi] += __expf(val - m_[bi]); }
                if (val > bv_[bi]) { bv_[bi] = val; bj_[bi] = pass*256 + jl; }
            }
        }
    }
    #pragma unroll
    for (int bi = 0; bi < 4; bi++) {
        float m = m_[bi], s = s_[bi], bv = bv_[bi];
        int bj = bj_[bi];
        #pragma unroll
        for (int o = 16; o > 0; o >>= 1) {
            float m2  = __shfl_xor_sync(0xffffffff, m, o);
            float s2  = __shfl_xor_sync(0xffffffff, s, o);
            float bv2 = __shfl_xor_sync(0xffffffff, bv, o);
            int   bj2 = __shfl_xor_sync(0xffffffff, bj, o);
            float mn = fmaxf(m, m2);
            s = s*__expf(m - mn) + s2*__expf(m2 - mn);
            m = mn;
            if (bv2 > bv || (bv2 == bv && bj2 < bj)) { bv = bv2; bj = bj2; }
        }
        if (lane == 0) {
            int b = w + 8*bi;
            int o = (r+1)*BATCH + b;
            g_rmax[o]  = m;
            g_marg[o]  = m + logf(s);
            g_rmaxi[o] = idx_s[bj];
        }
    }
}

// ---- per-batch verb marginals, norm, v_max, vr_maxi ----
__global__ void k_final(const float* __restrict__ vpot, const int* __restrict__ pad,
                        float* __restrict__ out_norm, float* __restrict__ out_vmax,
                        float* __restrict__ out_vrmaxi) {
    int b = blockIdx.x;
    __shared__ float ms[NR+1], xs2[NR+1];
    __shared__ int   is_[NR+1];
    __shared__ float vm_s[NV];
    __shared__ float red[256];
    int tid = threadIdx.x;
    for (int p = tid; p <= NR; p += 256) {
        ms[p]  = g_marg[p*BATCH + b];
        xs2[p] = g_rmax[p*BATCH + b];
        is_[p] = g_rmaxi[p*BATCH + b];
    }
    __syncthreads();
    for (int v = tid; v < NV; v += 256) {
        float vp = vpot[b*NV + v];
        float sm = vp, sx = vp;
        #pragma unroll
        for (int mm = 0; mm < MR; mm++) {
            int p = pad[v*MR + mm];
            sm += ms[p];
            sx += xs2[p];
            out_vrmaxi[(size_t)(b*NV + v)*MR + mm] = (float)is_[p];
        }
        vm_s[v] = sm;
        out_vmax[b*NV + v] = sx;
    }
    __syncthreads();
    float lm = -INFINITY;
    for (int v = tid; v < NV; v += 256) lm = fmaxf(lm, vm_s[v]);
    red[tid] = lm; __syncthreads();
    for (int o = 128; o > 0; o >>= 1) { if (tid < o) red[tid] = fmaxf(red[tid], red[tid+o]); __syncthreads(); }
    float gm = red[0]; __syncthreads();
    float ls = 0.f;
    for (int v = tid; v < NV; v += 256) ls += __expf(vm_s[v] - gm);
    red[tid] = ls; __syncthreads();
    for (int o = 128; o > 0; o >>= 1) { if (tid < o) red[tid] += red[tid+o]; __syncthreads(); }
    if (tid == 0) out_norm[b] = gm + logf(red[0]);
}

extern "C" void kernel_launch(void* const* d_in, const int* in_sizes, int n_in,
                              void* d_out, int out_size) {
    const float* rep = (const float*)d_in[0];
    const float* Wv  = (const float*)d_in[1];
    const float* bv  = (const float*)d_in[2];
    const float* Wr  = (const float*)d_in[3];
    const float* br  = (const float*)d_in[4];
    const float* aiw = (const float*)d_in[5];
    const float* aib = (const float*)d_in[6];
    const float* aow = (const float*)d_in[7];
    const float* aob = (const float*)d_in[8];
    const float* Wn  = (const float*)d_in[9];
    const float* bn  = (const float*)d_in[10];
    const int* rnidx = (const int*)d_in[11];
    const int* pad   = (const int*)d_in[12];
    float* out = (float*)d_out;

    dim3 g_gemm((NN + 255)/256, (NR*BATCH)/64);                                // (46, 95)

    k_front<<<300, 256>>>(rep, Wv, bv, Wr, br, aiw, aib, aow, aob, Wn, bn,
                          out + OFF_VPOT);                                     // 1
    k_attn<<<dim3(BATCH, NH), 768>>>(aiw, aib, 0, 0, 1);                       // 2
    k_attn<<<dim3(BATCH, NH), 768>>>(aiw, aib, 1, 1, 0);                       // 3
    // PROBE: dummy rngemm at profile slot #4 — reads layer-1 node (valid data,
    // wrong stage), writes out+OFF_RN which launch #6 fully overwrites.
    // Identical instruction mix & memory behavior to the real rngemm.
    k_rngemm<<<g_gemm, 256>>>(out + OFF_RN);                                   // 4  <-- profiled
    k_attn<<<dim3(BATCH, NH), 768>>>(aiw, aib, 2, 0, 1);                       // 5
    k_rngemm<<<g_gemm, 256>>>(out + OFF_RN);                                   // 6  (real)
    k_roles<<<NR, 256>>>(rnidx);                                               // 7
    k_final<<<BATCH, 256>>>(out + OFF_VPOT, pad,
                            out + OFF_NORM, out + OFF_VMAX, out + OFF_VRMAXI); // 8
    cudaMemcpyAsync(out + OFF_REP, rep, (size_t)BATCH*REPD*sizeof(float),
                    cudaMemcpyDeviceToDevice, 0);                              // 9
}

// round 14
// speedup vs baseline: 1.4764x; 1.4764x over previous
#include <cuda_runtime.h>
#include <math.h>

#define BATCH 32
#define REPD  1024
#define NV    504
#define NR    190
#define NN    11538
#define MR    6
#define HID   32
#define NH    4
#define HD    8
#define MAXN  512
#define LBH   (NR*BATCH*HID)

#define OFF_REP     0
#define OFF_VPOT    32768
#define OFF_RN      48896
#define OFF_NORM    70199936
#define OFF_VMAX    70199968
#define OFF_VRMAXI  70216096

__device__ float g_buf[2][LBH];
__device__ float g_marg[(NR+1)*BATCH];
__device__ float g_rmax[(NR+1)*BATCH];
__device__ int   g_rmaxi[(NR+1)*BATCH];
__device__ float g_wn[(size_t)HID*NN];     // fused Wn' [32][NN]
__device__ float g_wnT[(size_t)NN*HID];    // fused Wn' transposed [NN][32]
__device__ float g_bn[NN];                 // fused bn'
__device__ float g_iw[2*96*HID];           // fused in_w for layers 1,2
__device__ float g_ib[2*96];

__device__ __forceinline__ unsigned long long pack2dup(float x) {
    unsigned long long r;
    asm("mov.b64 %0, {%1, %1};" : "=l"(r) : "f"(x));
    return r;
}
__device__ __forceinline__ unsigned long long pack2(float x, float y) {
    unsigned long long r;
    asm("mov.b64 %0, {%1, %2};" : "=l"(r) : "f"(x), "f"(y));
    return r;
}
__device__ __forceinline__ void ffma2(unsigned long long &c, unsigned long long a, unsigned long long b) {
    asm("fma.rn.f32x2 %0, %1, %2, %0;" : "+l"(c) : "l"(a), "l"(b));
}
__device__ __forceinline__ float2 unpack2(unsigned long long v) {
    float2 f;
    asm("mov.b64 {%0, %1}, %2;" : "=f"(f.x), "=f"(f.y) : "l"(v));
    return f;
}

// =====================================================================
// launch 1 (k_front), 300 blocks x 256, 21.1KB smem union
// =====================================================================
__global__ __launch_bounds__(256) void k_front(
        const float* __restrict__ rep, const float* __restrict__ Wv,
        const float* __restrict__ bv, const float* __restrict__ Wr,
        const float* __restrict__ br, const float* __restrict__ aiw,
        const float* __restrict__ aib, const float* __restrict__ aow,
        const float* __restrict__ aob, const float* __restrict__ Wn,
        const float* __restrict__ bn, float* __restrict__ out_vpot) {
    __shared__ __align__(16) float S[5280];
    int tid = threadIdx.x;
    int bid = blockIdx.x;
    if (bid < 46) {
        float (*ows)[32] = reinterpret_cast<float(*)[32]>(S);   // [32][32]
        float *obs = S + 1024;
        for (int e = tid; e < 1024; e += 256) ows[e>>5][e&31] = aow[2*1024 + e];
        if (tid < 32) obs[tid] = aob[2*32 + tid];
        __syncthreads();
        int n = bid*256 + tid;
        if (n < NN) {
            float col[32];
            #pragma unroll
            for (int e = 0; e < 32; e++) col[e] = Wn[(size_t)e*NN + n];
            float wrow[32];
            #pragma unroll 4
            for (int f = 0; f < 32; f++) {
                float a = 0.f;
                #pragma unroll
                for (int e = 0; e < 32; e++) a = fmaf(ows[e][f], col[e], a);
                wrow[f] = a;
            }
            #pragma unroll
            for (int f = 0; f < 32; f++) {
                g_wn[(size_t)f*NN + n] = wrow[f];
                g_wnT[(size_t)n*32 + f] = wrow[f];
            }
            float bacc = bn[n];
            #pragma unroll
            for (int e = 0; e < 32; e++) bacc = fmaf(obs[e], col[e], bacc);
            g_bn[n] = bacc;
        }
        return;
    }
    if (bid < 109) {
        float (*rs)[132]  = reinterpret_cast<float(*)[132]>(S);          // [32][132]
        float (*wvT)[132] = reinterpret_cast<float(*)[132]>(S + 4224);   // [8][132]
        int vb = (bid - 46)*8;
        int b = tid >> 3, j = tid & 7;
        float acc = bv[vb + j];
        for (int kc = 0; kc < REPD; kc += 128) {
            for (int e = tid; e < 32*128; e += 256) {
                int bi = e >> 7, kk = e & 127;
                rs[bi][kk] = rep[bi*REPD + kc + kk];
            }
            for (int e = tid; e < 1024; e += 256) {
                int kk = e >> 3, jj = e & 7;
                wvT[jj][kk] = Wv[(size_t)(kc+kk)*NV + vb + jj];
            }
            __syncthreads();
            #pragma unroll 8
            for (int kk = 0; kk < 128; kk += 4) {
                float4 r4 = *reinterpret_cast<const float4*>(&rs[b][kk]);
                float4 w4 = *reinterpret_cast<const float4*>(&wvT[j][kk]);
                acc = fmaf(r4.x, w4.x, acc); acc = fmaf(r4.y, w4.y, acc);
                acc = fmaf(r4.z, w4.z, acc); acc = fmaf(r4.w, w4.w, acc);
            }
            __syncthreads();
        }
        out_vpot[b*NV + vb + j] = acc;
        return;
    }
    if (bid == 299) {
        float (*owp)[32][32] = reinterpret_cast<float(*)[32][32]>(S);     // [2][32][32]
        float (*obp)[32]     = reinterpret_cast<float(*)[32]>(S + 2048);  // [2][32]
        float (*aiws)[32]    = reinterpret_cast<float(*)[32]>(S + 2112);  // [96][32]
        for (int e = tid; e < 2048; e += 256) owp[e>>10][(e>>5)&31][e&31] = aow[e];
        if (tid < 64) obp[tid>>5][tid&31] = aob[tid];
        for (int jj = 0; jj < 2; jj++) {
            __syncthreads();
            for (int e = tid; e < 3072; e += 256) aiws[e>>5][e&31] = aiw[(jj+1)*3072 + e];
            __syncthreads();
            for (int t = tid; t < 3072; t += 256) {
                int r = t >> 5, f = t & 31;
                float a = 0.f;
                #pragma unroll
                for (int e = 0; e < 32; e++) a = fmaf(aiws[r][e], owp[jj][e][f], a);
                g_iw[jj*3072 + r*32 + f] = a;
            }
            if (tid < 96) {
                float a = aib[(jj+1)*96 + tid];
                #pragma unroll
                for (int e = 0; e < 32; e++) a = fmaf(aiws[tid][e], obp[jj][e], a);
                g_ib[jj*96 + tid] = a;
            }
        }
        return;
    }
    const int l = bid - 109;
    float (*rs2)[65] = reinterpret_cast<float(*)[65]>(S);          // [32][65]
    float (*ws2)[32] = reinterpret_cast<float(*)[32]>(S + 2080);   // [64][32]
    int bb = tid >> 3, hq = tid & 7;
    float c0 = 0.f, c1 = 0.f, c2 = 0.f, c3 = 0.f;
    for (int k0 = 0; k0 < REPD; k0 += 64) {
        for (int e = tid; e < 32*64; e += 256) {
            int bi = e >> 6, kk = e & 63;
            rs2[bi][kk] = rep[bi*REPD + k0 + kk];
        }
        for (int e = tid; e < 64*32; e += 256) {
            int kk = e >> 5, hh = e & 31;
            ws2[kk][hh] = Wr[(size_t)(k0+kk)*(NR*HID) + l*HID + hh];
        }
        __syncthreads();
        #pragma unroll 8
        for (int kk = 0; kk < 64; kk++) {
            float a = rs2[bb][kk];
            float4 w4 = *reinterpret_cast<const float4*>(&ws2[kk][hq*4]);
            c0 = fmaf(a, w4.x, c0); c1 = fmaf(a, w4.y, c1);
            c2 = fmaf(a, w4.z, c2); c3 = fmaf(a, w4.w, c3);
        }
        __syncthreads();
    }
    float* o = &g_buf[0][l*(BATCH*HID) + bb*HID];
    const float* bb_ = br + l*HID;
    o[hq*4+0] = c0 + bb_[hq*4+0];
    o[hq*4+1] = c1 + bb_[hq*4+1];
    o[hq*4+2] = c2 + bb_[hq*4+2];
    o[hq*4+3] = c3 + bb_[hq*4+3];
}

// =====================================================================
// attention per (b,h): 768 threads, 4 threads per query row (key-split),
// branchless two-pass softmax with smem partial merges
// =====================================================================
__global__ __launch_bounds__(768) void k_attn(const float* __restrict__ aiw,
                                              const float* __restrict__ aib,
                                              int layer, int src, int dst) {
    __shared__ __align__(16) float S[11840];
    float (*xs)[33]  = reinterpret_cast<float(*)[33]>(S);          // [190][33]
    float (*qs)[9]   = reinterpret_cast<float(*)[9]>(S + 6272);    // [190][9]
    float (*ks)[8]   = reinterpret_cast<float(*)[8]>(S + 7984);    // [190][8]
    float (*vs)[8]   = reinterpret_cast<float(*)[8]>(S + 9504);    // [190][8]
    float (*wsm)[32] = reinterpret_cast<float(*)[32]>(S + 11024);  // [24][32]
    float *bs        = S + 11792;                                   // [24]
    float *pmax      = S;                                           // [4*192]
    float *psum      = S + 768;                                     // [4*192]
    float (*po)[8]   = reinterpret_cast<float(*)[8]>(S + 1536);     // [4*192][8]

    int b = blockIdx.x, h = blockIdx.y;
    const float* w  = (layer == 0) ? aiw : (g_iw + (layer-1)*3072);
    const float* bi = (layer == 0) ? aib : (g_ib + (layer-1)*96);
    const float* x = &g_buf[src][0];
    int tid = threadIdx.x;            // 768
    int p = tid / 192;                // key-quarter 0..3
    int l = tid - p*192;              // query row 0..191

    for (int e = tid; e < NR*HID; e += 768) {
        int ll = e >> 5, c = e & 31;
        xs[ll][c] = x[ll*(BATCH*HID) + b*HID + c];
    }
    {
        int r = tid >> 5, c = tid & 31;
        if (r < 24) {
            int row = (r >> 3)*32 + h*8 + (r & 7);
            wsm[r][c] = w[row*HID + c];
        }
    }
    if (tid < 24) {
        int row = (tid >> 3)*32 + h*8 + (tid & 7);
        bs[tid] = bi[row];
    }
    __syncthreads();

    const float scale = 0.35355339059327373f;
    if (l < NR) {
        float xr[HID];
        #pragma unroll
        for (int e = 0; e < HID; e++) xr[e] = xs[l][e];
        #pragma unroll
        for (int rr = 0; rr < 6; rr++) {
            int r = p*6 + rr;
            float a = bs[r];
            #pragma unroll
            for (int e = 0; e < HID; e++) a = fmaf(xr[e], wsm[r][e], a);
            if (r < 8)       qs[l][r]    = a * scale;
            else if (r < 16) ks[l][r-8]  = a;
            else             vs[l][r-16] = a;
        }
    }
    __syncthreads();

    int m0 = p*48;
    int mend = (m0 + 48 < NR) ? (m0 + 48) : NR;
    float q[HD];
    float mx = -INFINITY;
    if (l < NR) {
        #pragma unroll
        for (int d = 0; d < HD; d++) q[d] = qs[l][d];
        #pragma unroll 4
        for (int m = m0; m < mend; m++) {
            const float4* k4 = reinterpret_cast<const float4*>(&ks[m][0]);
            float4 ka = k4[0], kb = k4[1];
            float sa = q[0]*ka.x + q[1]*ka.y;
            float sb = q[2]*ka.z + q[3]*ka.w;
            float sc = q[4]*kb.x + q[5]*kb.y;
            float sd = q[6]*kb.z + q[7]*kb.w;
            mx = fmaxf(mx, (sa+sb)+(sc+sd));
        }
        pmax[p*192 + l] = mx;
    }
    __syncthreads();

    float sum = 0.f;
    float o[HD] = {0,0,0,0,0,0,0,0};
    if (l < NR) {
        float gm = fmaxf(fmaxf(pmax[l], pmax[192+l]), fmaxf(pmax[384+l], pmax[576+l]));
        #pragma unroll 4
        for (int m = m0; m < mend; m++) {
            const float4* k4 = reinterpret_cast<const float4*>(&ks[m][0]);
            float4 ka = k4[0], kb = k4[1];
            float sa = q[0]*ka.x + q[1]*ka.y;
            float sb = q[2]*ka.z + q[3]*ka.w;
            float sc = q[4]*kb.x + q[5]*kb.y;
            float sd = q[6]*kb.z + q[7]*kb.w;
            float pe = __expf((sa+sb)+(sc+sd) - gm);
            sum += pe;
            const float4* v4 = reinterpret_cast<const float4*>(&vs[m][0]);
            float4 va = v4[0], vb4 = v4[1];
            o[0] = fmaf(pe, va.x, o[0]);  o[1] = fmaf(pe, va.y, o[1]);
            o[2] = fmaf(pe, va.z, o[2]);  o[3] = fmaf(pe, va.w, o[3]);
            o[4] = fmaf(pe, vb4.x, o[4]); o[5] = fmaf(pe, vb4.y, o[5]);
            o[6] = fmaf(pe, vb4.z, o[6]); o[7] = fmaf(pe, vb4.w, o[7]);
        }
        psum[p*192 + l] = sum;
        #pragma unroll
        for (int d = 0; d < HD; d++) po[p*192 + l][d] = o[d];
    }
    __syncthreads();

    if (l < NR) {
        float st = psum[l] + psum[192+l] + psum[384+l] + psum[576+l];
        float inv = 1.0f / st;
        float* dp = &g_buf[dst][l*(BATCH*HID) + b*HID + h*HD];
        #pragma unroll
        for (int dd = 0; dd < 2; dd++) {
            int d = p*2 + dd;
            dp[d] = (po[l][d] + po[192+l][d] + po[384+l][d] + po[576+l][d]) * inv;
        }
    }
}

// ---- rn = ctx2 @ Wn' + bn'  (M=6080, N=11538, K=32), FFMA2
//      512 threads, 4m x 8n per thread -> ~60 regs -> 2 blocks/SM (32 warps) ----
__global__ __launch_bounds__(512, 2) void k_rngemm(float* __restrict__ out) {
    const int m0 = blockIdx.y * 64;
    const int n0 = blockIdx.x * 256;
    __shared__ __align__(16) float aT[32][68];
    __shared__ __align__(16) float wsm[32][256];
    const float* A = &g_buf[1][0];
    int tid = threadIdx.x;            // 512
    int tx = tid & 31, ty = tid >> 5; // ty 0..15
    for (int e = tid; e < 64*32; e += 512) {
        int m = e >> 5, k = e & 31;
        aT[k][m] = A[(m0+m)*32 + k];
    }
    for (int e = tid; e < 32*256; e += 512) {
        int k = e >> 8, n = e & 255;
        int gn = n0 + n;
        wsm[k][n] = (gn < NN) ? g_wn[(size_t)k*NN + gn] : 0.0f;
    }
    __syncthreads();

    unsigned long long c[4][4];
    #pragma unroll
    for (int q = 0; q < 4; q++) {
        int gn = n0 + 2*tx + 64*q;
        float b0 = (gn   < NN) ? g_bn[gn]   : 0.f;
        float b1 = (gn+1 < NN) ? g_bn[gn+1] : 0.f;
        unsigned long long bp = pack2(b0, b1);
        #pragma unroll
        for (int i = 0; i < 4; i++) c[i][q] = bp;
    }
    const int mb = ty*4;              // 4 m-rows per thread
    #pragma unroll 8
    for (int k = 0; k < 32; k++) {
        float4 a0 = *reinterpret_cast<const float4*>(&aT[k][mb]);
        unsigned long long Aa[4];
        Aa[0] = pack2dup(a0.x); Aa[1] = pack2dup(a0.y);
        Aa[2] = pack2dup(a0.z); Aa[3] = pack2dup(a0.w);
        unsigned long long Bb[4];
        Bb[0] = *reinterpret_cast<const unsigned long long*>(&wsm[k][2*tx]);
        Bb[1] = *reinterpret_cast<const unsigned long long*>(&wsm[k][2*tx+64]);
        Bb[2] = *reinterpret_cast<const unsigned long long*>(&wsm[k][2*tx+128]);
        Bb[3] = *reinterpret_cast<const unsigned long long*>(&wsm[k][2*tx+192]);
        #pragma unroll
        for (int i = 0; i < 4; i++) {
            #pragma unroll
            for (int q = 0; q < 4; q++) ffma2(c[i][q], Aa[i], Bb[q]);
        }
    }
    #pragma unroll
    for (int i = 0; i < 4; i++) {
        size_t row = (size_t)(m0 + mb + i) * NN;
        #pragma unroll
        for (int q = 0; q < 4; q++) {
            int gn = n0 + 2*tx + 64*q;
            float2 pv = unpack2(c[i][q]);
            if (gn + 1 < NN)  __stcs(reinterpret_cast<float2*>(&out[row + gn]), pv);
            else if (gn < NN) __stcs(&out[row + gn], pv.x);
        }
    }
}

// ---- per-role: recompute gathered logits from L2-resident WnT ----
__global__ void k_roles(const int* __restrict__ rnidx) {
    int r = blockIdx.x;
    __shared__ int idx_s[MAXN];
    __shared__ float node_s[32][33];
    __shared__ float colsm[256][33];
    __shared__ float bns[256];
    int tid = threadIdx.x;  // 256
    for (int e = tid; e < MAXN; e += 256) idx_s[e] = rnidx[r*MAXN + e];
    for (int e = tid; e < 1024; e += 256) node_s[e>>5][e&31] = g_buf[1][r*(BATCH*HID) + e];
    if (r == 0 && tid < BATCH) { g_marg[tid] = 0.f; g_rmax[tid] = 0.f; g_rmaxi[tid] = 0; }
    int w = tid >> 5, lane = tid & 31;
    float m_[4], s_[4], bv_[4];
    int bj_[4];
    #pragma unroll
    for (int i = 0; i < 4; i++) { m_[i] = -INFINITY; s_[i] = 0.f; bv_[i] = -INFINITY; bj_[i] = 0; }
    for (int pass = 0; pass < 2; pass++) {
        __syncthreads();
        for (int e = tid; e < 256*8; e += 256) {
            int jl = e >> 3, q = e & 7;
            const float4* srcp = reinterpret_cast<const float4*>(g_wnT + (size_t)idx_s[pass*256 + jl]*32);
            float4 v = srcp[q];
            colsm[jl][q*4+0] = v.x; colsm[jl][q*4+1] = v.y;
            colsm[jl][q*4+2] = v.z; colsm[jl][q*4+3] = v.w;
        }
        bns[tid] = g_bn[idx_s[pass*256 + tid]];
        __syncthreads();
        #pragma unroll
        for (int bi = 0; bi < 4; bi++) {
            int b = w + 8*bi;
            float nb[32];
            #pragma unroll
            for (int k = 0; k < 32; k++) nb[k] = node_s[b][k];
            for (int q = 0; q < 8; q++) {
                int jl = q*32 + lane;
                float val = bns[jl];
                #pragma unroll
                for (int k = 0; k < 32; k++) val = fmaf(nb[k], colsm[jl][k], val);
                if (val > m_[bi]) { s_[bi] = s_[bi]*__expf(m_[bi] - val) + 1.f; m_[bi] = val; }
                else              { s_[bi] += __expf(val - m_[bi]); }
                if (val > bv_[bi]) { bv_[bi] = val; bj_[bi] = pass*256 + jl; }
            }
        }
    }
    #pragma unroll
    for (int bi = 0; bi < 4; bi++) {
        float m = m_[bi], s = s_[bi], bv = bv_[bi];
        int bj = bj_[bi];
        #pragma unroll
        for (int o = 16; o > 0; o >>= 1) {
            float m2  = __shfl_xor_sync(0xffffffff, m, o);
            float s2  = __shfl_xor_sync(0xffffffff, s, o);
            float bv2 = __shfl_xor_sync(0xffffffff, bv, o);
            int   bj2 = __shfl_xor_sync(0xffffffff, bj, o);
            float mn = fmaxf(m, m2);
            s = s*__expf(m - mn) + s2*__expf(m2 - mn);
            m = mn;
            if (bv2 > bv || (bv2 == bv && bj2 < bj)) { bv = bv2; bj = bj2; }
        }
        if (lane == 0) {
            int b = w + 8*bi;
            int o = (r+1)*BATCH + b;
            g_rmax[o]  = m;
            g_marg[o]  = m + logf(s);
            g_rmaxi[o] = idx_s[bj];
        }
    }
}

// ---- per-batch verb marginals, norm, v_max, vr_maxi ----
__global__ void k_final(const float* __restrict__ vpot, const int* __restrict__ pad,
                        float* __restrict__ out_norm, float* __restrict__ out_vmax,
                        float* __restrict__ out_vrmaxi) {
    int b = blockIdx.x;
    __shared__ float ms[NR+1], xs2[NR+1];
    __shared__ int   is_[NR+1];
    __shared__ float vm_s[NV];
    __shared__ float red[256];
    int tid = threadIdx.x;
    for (int p = tid; p <= NR; p += 256) {
        ms[p]  = g_marg[p*BATCH + b];
        xs2[p] = g_rmax[p*BATCH + b];
        is_[p] = g_rmaxi[p*BATCH + b];
    }
    __syncthreads();
    for (int v = tid; v < NV; v += 256) {
        float vp = vpot[b*NV + v];
        float sm = vp, sx = vp;
        #pragma unroll
        for (int mm = 0; mm < MR; mm++) {
            int p = pad[v*MR + mm];
            sm += ms[p];
            sx += xs2[p];
            out_vrmaxi[(size_t)(b*NV + v)*MR + mm] = (float)is_[p];
        }
        vm_s[v] = sm;
        out_vmax[b*NV + v] = sx;
    }
    __syncthreads();
    float lm = -INFINITY;
    for (int v = tid; v < NV; v += 256) lm = fmaxf(lm, vm_s[v]);
    red[tid] = lm; __syncthreads();
    for (int o = 128; o > 0; o >>= 1) { if (tid < o) red[tid] = fmaxf(red[tid], red[tid+o]); __syncthreads(); }
    float gm = red[0]; __syncthreads();
    float ls = 0.f;
    for (int v = tid; v < NV; v += 256) ls += __expf(vm_s[v] - gm);
    red[tid] = ls; __syncthreads();
    for (int o = 128; o > 0; o >>= 1) { if (tid < o) red[tid] += red[tid+o]; __syncthreads(); }
    if (tid == 0) out_norm[b] = gm + logf(red[0]);
}

extern "C" void kernel_launch(void* const* d_in, const int* in_sizes, int n_in,
                              void* d_out, int out_size) {
    const float* rep = (const float*)d_in[0];
    const float* Wv  = (const float*)d_in[1];
    const float* bv  = (const float*)d_in[2];
    const float* Wr  = (const float*)d_in[3];
    const float* br  = (const float*)d_in[4];
    const float* aiw = (const float*)d_in[5];
    const float* aib = (const float*)d_in[6];
    const float* aow = (const float*)d_in[7];
    const float* aob = (const float*)d_in[8];
    const float* Wn  = (const float*)d_in[9];
    const float* bn  = (const float*)d_in[10];
    const int* rnidx = (const int*)d_in[11];
    const int* pad   = (const int*)d_in[12];
    float* out = (float*)d_out;

    k_front<<<300, 256>>>(rep, Wv, bv, Wr, br, aiw, aib, aow, aob, Wn, bn,
                          out + OFF_VPOT);                                     // 1
    k_attn<<<dim3(BATCH, NH), 768>>>(aiw, aib, 0, 0, 1);                       // 2
    k_attn<<<dim3(BATCH, NH), 768>>>(aiw, aib, 1, 1, 0);                       // 3
    k_attn<<<dim3(BATCH, NH), 768>>>(aiw, aib, 2, 0, 1);                       // 4
    dim3 g_gemm((NN + 255)/256, (NR*BATCH)/64);                                // (46, 95)
    k_rngemm<<<g_gemm, 512>>>(out + OFF_RN);                                   // 5
    k_roles<<<NR, 256>>>(rnidx);                                               // 6
    k_final<<<BATCH, 256>>>(out + OFF_VPOT, pad,
                            out + OFF_NORM, out + OFF_VMAX, out + OFF_VRMAXI); // 7
    cudaMemcpyAsync(out + OFF_REP, rep, (size_t)BATCH*REPD*sizeof(float),
                    cudaMemcpyDeviceToDevice, 0);                              // 8
}

// round 16
// speedup vs baseline: 1.6763x; 1.1354x over previous
#include <cuda_runtime.h>
#include <cuda_bf16.h>
#include <math.h>

#define BATCH 32
#define REPD  1024
#define NV    504
#define NR    190
#define NN    11538
#define MR    6
#define HID   32
#define NH    4
#define HD    8
#define MAXN  512
#define LBH   (NR*BATCH*HID)

#define OFF_REP     0
#define OFF_VPOT    32768
#define OFF_RN      48896
#define OFF_NORM    70199936
#define OFF_VMAX    70199968
#define OFF_VRMAXI  70216096

__device__ float g_buf[2][LBH];
__device__ float g_marg[(NR+1)*BATCH];
__device__ float g_rmax[(NR+1)*BATCH];
__device__ int   g_rmaxi[(NR+1)*BATCH];
__device__ float g_wnT[(size_t)NN*HID];           // fused Wn' transposed [NN][32] fp32 (roles)
__device__ unsigned int g_wnT_h32[(size_t)NN*16]; // bf16-hi pairs [NN][16 words]
__device__ unsigned int g_wnT_l32[(size_t)NN*16]; // bf16-lo pairs
__device__ float g_bn[NN];
__device__ float g_iw[2*96*HID];
__device__ float g_ib[2*96];

#define MMA_BF16(c, a, b) \
    asm volatile("mma.sync.aligned.m16n8k16.row.col.f32.bf16.bf16.f32 " \
        "{%0,%1,%2,%3}, {%4,%5,%6,%7}, {%8,%9}, {%0,%1,%2,%3};" \
        : "+f"((c)[0]), "+f"((c)[1]), "+f"((c)[2]), "+f"((c)[3]) \
        : "r"((a)[0]), "r"((a)[1]), "r"((a)[2]), "r"((a)[3]), \
          "r"((b)[0]), "r"((b)[1]))

// =====================================================================
// launch 1 (k_front): bid 0..45 Wn-fuse(+bf16 split) | 46..108 vpot |
//                     109..298 node0 | 299 iw-fuse
// =====================================================================
__global__ __launch_bounds__(256) void k_front(
        const float* __restrict__ rep, const float* __restrict__ Wv,
        const float* __restrict__ bv, const float* __restrict__ Wr,
        const float* __restrict__ br, const float* __restrict__ aiw,
        const float* __restrict__ aib, const float* __restrict__ aow,
        const float* __restrict__ aob, const float* __restrict__ Wn,
        const float* __restrict__ bn, float* __restrict__ out_vpot) {
    __shared__ __align__(16) float S[5280];
    int tid = threadIdx.x;
    int bid = blockIdx.x;
    if (bid < 46) {
        float (*ows)[32] = reinterpret_cast<float(*)[32]>(S);
        float *obs = S + 1024;
        for (int e = tid; e < 1024; e += 256) ows[e>>5][e&31] = aow[2*1024 + e];
        if (tid < 32) obs[tid] = aob[2*32 + tid];
        __syncthreads();
        int n = bid*256 + tid;
        if (n < NN) {
            float col[32];
            #pragma unroll
            for (int e = 0; e < 32; e++) col[e] = Wn[(size_t)e*NN + n];
            float wrow[32];
            #pragma unroll 4
            for (int f = 0; f < 32; f++) {
                float a = 0.f;
                #pragma unroll
                for (int e = 0; e < 32; e++) a = fmaf(ows[e][f], col[e], a);
                wrow[f] = a;
            }
            #pragma unroll
            for (int f = 0; f < 32; f += 2) {
                g_wnT[(size_t)n*32 + f]   = wrow[f];
                g_wnT[(size_t)n*32 + f+1] = wrow[f+1];
                __nv_bfloat16 h0 = __float2bfloat16(wrow[f]);
                __nv_bfloat16 h1 = __float2bfloat16(wrow[f+1]);
                __nv_bfloat16 l0 = __float2bfloat16(wrow[f]   - __bfloat162float(h0));
                __nv_bfloat16 l1 = __float2bfloat16(wrow[f+1] - __bfloat162float(h1));
                g_wnT_h32[(size_t)n*16 + (f>>1)] =
                    (unsigned)__bfloat16_as_ushort(h0) | ((unsigned)__bfloat16_as_ushort(h1) << 16);
                g_wnT_l32[(size_t)n*16 + (f>>1)] =
                    (unsigned)__bfloat16_as_ushort(l0) | ((unsigned)__bfloat16_as_ushort(l1) << 16);
            }
            float bacc = bn[n];
            #pragma unroll
            for (int e = 0; e < 32; e++) bacc = fmaf(obs[e], col[e], bacc);
            g_bn[n] = bacc;
        }
        return;
    }
    if (bid < 109) {
        float (*rs)[132]  = reinterpret_cast<float(*)[132]>(S);
        float (*wvT)[132] = reinterpret_cast<float(*)[132]>(S + 4224);
        int vb = (bid - 46)*8;
        int b = tid >> 3, j = tid & 7;
        float acc = bv[vb + j];
        for (int kc = 0; kc < REPD; kc += 128) {
            for (int e = tid; e < 32*128; e += 256) {
                int bi = e >> 7, kk = e & 127;
                rs[bi][kk] = rep[bi*REPD + kc + kk];
            }
            for (int e = tid; e < 1024; e += 256) {
                int kk = e >> 3, jj = e & 7;
                wvT[jj][kk] = Wv[(size_t)(kc+kk)*NV + vb + jj];
            }
            __syncthreads();
            #pragma unroll 8
            for (int kk = 0; kk < 128; kk += 4) {
                float4 r4 = *reinterpret_cast<const float4*>(&rs[b][kk]);
                float4 w4 = *reinterpret_cast<const float4*>(&wvT[j][kk]);
                acc = fmaf(r4.x, w4.x, acc); acc = fmaf(r4.y, w4.y, acc);
                acc = fmaf(r4.z, w4.z, acc); acc = fmaf(r4.w, w4.w, acc);
            }
            __syncthreads();
        }
        out_vpot[b*NV + vb + j] = acc;
        return;
    }
    if (bid == 299) {
        float (*owp)[32][32] = reinterpret_cast<float(*)[32][32]>(S);
        float (*obp)[32]     = reinterpret_cast<float(*)[32]>(S + 2048);
        float (*aiws)[32]    = reinterpret_cast<float(*)[32]>(S + 2112);
        for (int e = tid; e < 2048; e += 256) owp[e>>10][(e>>5)&31][e&31] = aow[e];
        if (tid < 64) obp[tid>>5][tid&31] = aob[tid];
        for (int jj = 0; jj < 2; jj++) {
            __syncthreads();
            for (int e = tid; e < 3072; e += 256) aiws[e>>5][e&31] = aiw[(jj+1)*3072 + e];
            __syncthreads();
            for (int t = tid; t < 3072; t += 256) {
                int r = t >> 5, f = t & 31;
                float a = 0.f;
                #pragma unroll
                for (int e = 0; e < 32; e++) a = fmaf(aiws[r][e], owp[jj][e][f], a);
                g_iw[jj*3072 + r*32 + f] = a;
            }
            if (tid < 96) {
                float a = aib[(jj+1)*96 + tid];
                #pragma unroll
                for (int e = 0; e < 32; e++) a = fmaf(aiws[tid][e], obp[jj][e], a);
                g_ib[jj*96 + tid] = a;
            }
        }
        return;
    }
    const int l = bid - 109;
    float (*rs2)[65] = reinterpret_cast<float(*)[65]>(S);
    float (*ws2)[32] = reinterpret_cast<float(*)[32]>(S + 2080);
    int bb = tid >> 3, hq = tid & 7;
    float c0 = 0.f, c1 = 0.f, c2 = 0.f, c3 = 0.f;
    for (int k0 = 0; k0 < REPD; k0 += 64) {
        for (int e = tid; e < 32*64; e += 256) {
            int bi = e >> 6, kk = e & 63;
            rs2[bi][kk] = rep[bi*REPD + k0 + kk];
        }
        for (int e = tid; e < 64*32; e += 256) {
            int kk = e >> 5, hh = e & 31;
            ws2[kk][hh] = Wr[(size_t)(k0+kk)*(NR*HID) + l*HID + hh];
        }
        __syncthreads();
        #pragma unroll 8
        for (int kk = 0; kk < 64; kk++) {
            float a = rs2[bb][kk];
            float4 w4 = *reinterpret_cast<const float4*>(&ws2[kk][hq*4]);
            c0 = fmaf(a, w4.x, c0); c1 = fmaf(a, w4.y, c1);
            c2 = fmaf(a, w4.z, c2); c3 = fmaf(a, w4.w, c3);
        }
        __syncthreads();
    }
    float* o = &g_buf[0][l*(BATCH*HID) + bb*HID];
    const float* bb_ = br + l*HID;
    o[hq*4+0] = c0 + bb_[hq*4+0];
    o[hq*4+1] = c1 + bb_[hq*4+1];
    o[hq*4+2] = c2 + bb_[hq*4+2];
    o[hq*4+3] = c3 + bb_[hq*4+3];
}

// =====================================================================
// attention per (b,h): 768 threads, 4-way key split, branchless 2-pass
// =====================================================================
__global__ __launch_bounds__(768) void k_attn(const float* __restrict__ aiw,
                                              const float* __restrict__ aib,
                                              int layer, int src, int dst) {
    __shared__ __align__(16) float S[11840];
    float (*xs)[33]  = reinterpret_cast<float(*)[33]>(S);
    float (*qs)[9]   = reinterpret_cast<float(*)[9]>(S + 6272);
    float (*ks)[8]   = reinterpret_cast<float(*)[8]>(S + 7984);
    float (*vs)[8]   = reinterpret_cast<float(*)[8]>(S + 9504);
    float (*wsm)[32] = reinterpret_cast<float(*)[32]>(S + 11024);
    float *bs        = S + 11792;
    float *pmax      = S;
    float *psum      = S + 768;
    float (*po)[8]   = reinterpret_cast<float(*)[8]>(S + 1536);

    int b = blockIdx.x, h = blockIdx.y;
    const float* w  = (layer == 0) ? aiw : (g_iw + (layer-1)*3072);
    const float* bi = (layer == 0) ? aib : (g_ib + (layer-1)*96);
    const float* x = &g_buf[src][0];
    int tid = threadIdx.x;
    int p = tid / 192;
    int l = tid - p*192;

    for (int e = tid; e < NR*HID; e += 768) {
        int ll = e >> 5, c = e & 31;
        xs[ll][c] = x[ll*(BATCH*HID) + b*HID + c];
    }
    {
        int r = tid >> 5, c = tid & 31;
        if (r < 24) {
            int row = (r >> 3)*32 + h*8 + (r & 7);
            wsm[r][c] = w[row*HID + c];
        }
    }
    if (tid < 24) {
        int row = (tid >> 3)*32 + h*8 + (tid & 7);
        bs[tid] = bi[row];
    }
    __syncthreads();

    const float scale = 0.35355339059327373f;
    if (l < NR) {
        float xr[HID];
        #pragma unroll
        for (int e = 0; e < HID; e++) xr[e] = xs[l][e];
        #pragma unroll
        for (int rr = 0; rr < 6; rr++) {
            int r = p*6 + rr;
            float a = bs[r];
            #pragma unroll
            for (int e = 0; e < HID; e++) a = fmaf(xr[e], wsm[r][e], a);
            if (r < 8)       qs[l][r]    = a * scale;
            else if (r < 16) ks[l][r-8]  = a;
            else             vs[l][r-16] = a;
        }
    }
    __syncthreads();

    int m0 = p*48;
    int mend = (m0 + 48 < NR) ? (m0 + 48) : NR;
    float q[HD];
    float mx = -INFINITY;
    if (l < NR) {
        #pragma unroll
        for (int d = 0; d < HD; d++) q[d] = qs[l][d];
        #pragma unroll 4
        for (int m = m0; m < mend; m++) {
            const float4* k4 = reinterpret_cast<const float4*>(&ks[m][0]);
            float4 ka = k4[0], kb = k4[1];
            float sa = q[0]*ka.x + q[1]*ka.y;
            float sb = q[2]*ka.z + q[3]*ka.w;
            float sc = q[4]*kb.x + q[5]*kb.y;
            float sd = q[6]*kb.z + q[7]*kb.w;
            mx = fmaxf(mx, (sa+sb)+(sc+sd));
        }
        pmax[p*192 + l] = mx;
    }
    __syncthreads();

    float sum = 0.f;
    float o[HD] = {0,0,0,0,0,0,0,0};
    if (l < NR) {
        float gm = fmaxf(fmaxf(pmax[l], pmax[192+l]), fmaxf(pmax[384+l], pmax[576+l]));
        #pragma unroll 4
        for (int m = m0; m < mend; m++) {
            const float4* k4 = reinterpret_cast<const float4*>(&ks[m][0]);
            float4 ka = k4[0], kb = k4[1];
            float sa = q[0]*ka.x + q[1]*ka.y;
            float sb = q[2]*ka.z + q[3]*ka.w;
            float sc = q[4]*kb.x + q[5]*kb.y;
            float sd = q[6]*kb.z + q[7]*kb.w;
            float pe = __expf((sa+sb)+(sc+sd) - gm);
            sum += pe;
            const float4* v4 = reinterpret_cast<const float4*>(&vs[m][0]);
            float4 va = v4[0], vb4 = v4[1];
            o[0] = fmaf(pe, va.x, o[0]);  o[1] = fmaf(pe, va.y, o[1]);
            o[2] = fmaf(pe, va.z, o[2]);  o[3] = fmaf(pe, va.w, o[3]);
            o[4] = fmaf(pe, vb4.x, o[4]); o[5] = fmaf(pe, vb4.y, o[5]);
            o[6] = fmaf(pe, vb4.z, o[6]); o[7] = fmaf(pe, vb4.w, o[7]);
        }
        psum[p*192 + l] = sum;
        #pragma unroll
        for (int d = 0; d < HD; d++) po[p*192 + l][d] = o[d];
    }
    __syncthreads();

    if (l < NR) {
        float st = psum[l] + psum[192+l] + psum[384+l] + psum[576+l];
        float inv = 1.0f / st;
        float* dp = &g_buf[dst][l*(BATCH*HID) + b*HID + h*HD];
        #pragma unroll
        for (int dd = 0; dd < 2; dd++) {
            int d = p*2 + dd;
            dp[d] = (po[l][d] + po[192+l][d] + po[384+l][d] + po[576+l][d]) * inv;
        }
    }
}

// =====================================================================
// rn GEMM via mma.sync bf16 3-term split: block 64m x 128n x K32,
// 256 threads = 8 warps (4m x 2n), warp tile m16 x n64
// =====================================================================
__global__ __launch_bounds__(256) void k_rngemm_mma(float* __restrict__ out) {
    __shared__ __align__(16) __nv_bfloat16 Ah[64][40];
    __shared__ __align__(16) __nv_bfloat16 Al[64][40];
    __shared__ __align__(16) __nv_bfloat16 Bh[128][40];
    __shared__ __align__(16) __nv_bfloat16 Bl[128][40];
    __shared__ float bias[128];
    const int m0 = blockIdx.y * 64;
    const int n0 = blockIdx.x * 128;
    int tid = threadIdx.x, wid = tid >> 5, lane = tid & 31;

    for (int e = tid; e < 2048; e += 256) {
        int m = e >> 5, k = e & 31;
        float f = g_buf[1][(size_t)(m0 + m)*32 + k];
        __nv_bfloat16 h = __float2bfloat16(f);
        __nv_bfloat16 l = __float2bfloat16(f - __bfloat162float(h));
        Ah[m][k] = h;
        Al[m][k] = l;
    }
    for (int e = tid; e < 2048; e += 256) {
        int n = e >> 4, wd = e & 15;
        unsigned hw = 0, lw = 0;
        if (n0 + n < NN) {
            hw = g_wnT_h32[(size_t)(n0 + n)*16 + wd];
            lw = g_wnT_l32[(size_t)(n0 + n)*16 + wd];
        }
        *reinterpret_cast<unsigned*>(&Bh[n][wd*2]) = hw;
        *reinterpret_cast<unsigned*>(&Bl[n][wd*2]) = lw;
    }
    if (tid < 128) bias[tid] = (n0 + tid < NN) ? g_bn[n0 + tid] : 0.f;
    __syncthreads();

    int wm = wid & 3, wn = wid >> 2;
    int mrow = wm * 16, nbase = wn * 64;
    float c[8][4];
    #pragma unroll
    for (int nb = 0; nb < 8; nb++) {
        c[nb][0] = 0.f; c[nb][1] = 0.f; c[nb][2] = 0.f; c[nb][3] = 0.f;
    }

    // ldmatrix lane addressing
    int ag = lane >> 3;                               // 0..3
    int arow = mrow + (lane & 7) + (ag & 1)*8;        // m row
    int akof = (ag >> 1)*8;                           // k offset within 16
    int brow_l = (lane & 7);                          // n within 8-block
    int bsel = (lane >> 3) & 1;                       // k half for B

    #pragma unroll
    for (int ksx = 0; ksx < 2; ksx++) {
        unsigned ah[4], alr[4];
        unsigned aaddr = (unsigned)__cvta_generic_to_shared(&Ah[arow][ksx*16 + akof]);
        asm volatile("ldmatrix.sync.aligned.m8n8.x4.shared.b16 {%0,%1,%2,%3}, [%4];"
                     : "=r"(ah[0]), "=r"(ah[1]), "=r"(ah[2]), "=r"(ah[3]) : "r"(aaddr));
        unsigned aaddr2 = (unsigned)__cvta_generic_to_shared(&Al[arow][ksx*16 + akof]);
        asm volatile("ldmatrix.sync.aligned.m8n8.x4.shared.b16 {%0,%1,%2,%3}, [%4];"
                     : "=r"(alr[0]), "=r"(alr[1]), "=r"(alr[2]), "=r"(alr[3]) : "r"(aaddr2));
        #pragma unroll
        for (int nb = 0; nb < 8; nb++) {
            unsigned bh[2], bl2[2];
            unsigned baddr = (unsigned)__cvta_generic_to_shared(
                &Bh[nbase + nb*8 + brow_l][ksx*16 + bsel*8]);
            asm volatile("ldmatrix.sync.aligned.m8n8.x2.shared.b16 {%0,%1}, [%2];"
                         : "=r"(bh[0]), "=r"(bh[1]) : "r"(baddr));
            unsigned baddr2 = (unsigned)__cvta_generic_to_shared(
                &Bl[nbase + nb*8 + brow_l][ksx*16 + bsel*8]);
            asm volatile("ldmatrix.sync.aligned.m8n8.x2.shared.b16 {%0,%1}, [%2];"
                         : "=r"(bl2[0]), "=r"(bl2[1]) : "r"(baddr2));
            MMA_BF16(c[nb], ah, bh);
            MMA_BF16(c[nb], ah, bl2);
            MMA_BF16(c[nb], alr, bh);
        }
    }

    // epilogue: D fragment rows lane/4 and lane/4+8, cols 2*(lane%4)+{0,1}
    int r0 = m0 + mrow + (lane >> 2);
    int r1 = r0 + 8;
    int cb = 2*(lane & 3);
    size_t rb0 = (size_t)r0 * NN;
    size_t rb1 = (size_t)r1 * NN;
    #pragma unroll
    for (int nb = 0; nb < 8; nb++) {
        int nl = nbase + nb*8 + cb;
        int n = n0 + nl;
        float bv0 = bias[nl], bv1 = bias[nl + 1];
        float v0 = c[nb][0] + bv0, v1 = c[nb][1] + bv1;
        float v2 = c[nb][2] + bv0, v3 = c[nb][3] + bv1;
        if (n + 1 < NN) {
            __stcs(reinterpret_cast<float2*>(&out[rb0 + n]), make_float2(v0, v1));
            __stcs(reinterpret_cast<float2*>(&out[rb1 + n]), make_float2(v2, v3));
        } else if (n < NN) {
            __stcs(&out[rb0 + n], v0);
            __stcs(&out[rb1 + n], v2);
        }
    }
}

// ---- per-role: recompute gathered logits from L2-resident WnT (fp32) ----
__global__ void k_roles(const int* __restrict__ rnidx) {
    int r = blockIdx.x;
    __shared__ int idx_s[MAXN];
    __shared__ float node_s[32][33];
    __shared__ float colsm[256][33];
    __shared__ float bns[256];
    int tid = threadIdx.x;
    for (int e = tid; e < MAXN; e += 256) idx_s[e] = rnidx[r*MAXN + e];
    for (int e = tid; e < 1024; e += 256) node_s[e>>5][e&31] = g_buf[1][r*(BATCH*HID) + e];
    if (r == 0 && tid < BATCH) { g_marg[tid] = 0.f; g_rmax[tid] = 0.f; g_rmaxi[tid] = 0; }
    int w = tid >> 5, lane = tid & 31;
    float m_[4], s_[4], bv_[4];
    int bj_[4];
    #pragma unroll
    for (int i = 0; i < 4; i++) { m_[i] = -INFINITY; s_[i] = 0.f; bv_[i] = -INFINITY; bj_[i] = 0; }
    for (int pass = 0; pass < 2; pass++) {
        __syncthreads();
        for (int e = tid; e < 256*8; e += 256) {
            int jl = e >> 3, q = e & 7;
            const float4* srcp = reinterpret_cast<const float4*>(g_wnT + (size_t)idx_s[pass*256 + jl]*32);
            float4 v = srcp[q];
            colsm[jl][q*4+0] = v.x; colsm[jl][q*4+1] = v.y;
            colsm[jl][q*4+2] = v.z; colsm[jl][q*4+3] = v.w;
        }
        bns[tid] = g_bn[idx_s[pass*256 + tid]];
        __syncthreads();
        #pragma unroll
        for (int bi = 0; bi < 4; bi++) {
            int b = w + 8*bi;
            float nb[32];
            #pragma unroll
            for (int k = 0; k < 32; k++) nb[k] = node_s[b][k];
            for (int q = 0; q < 8; q++) {
                int jl = q*32 + lane;
                float val = bns[jl];
                #pragma unroll
                for (int k = 0; k < 32; k++) val = fmaf(nb[k], colsm[jl][k], val);
                if (val > m_[bi]) { s_[bi] = s_[bi]*__expf(m_[bi] - val) + 1.f; m_[bi] = val; }
                else              { s_[bi] += __expf(val - m_[bi]); }
                if (val > bv_[bi]) { bv_[bi] = val; bj_[bi] = pass*256 + jl; }
            }
        }
    }
    #pragma unroll
    for (int bi = 0; bi < 4; bi++) {
        float m = m_[bi], s = s_[bi], bv = bv_[bi];
        int bj = bj_[bi];
        #pragma unroll
        for (int o = 16; o > 0; o >>= 1) {
            float m2  = __shfl_xor_sync(0xffffffff, m, o);
            float s2  = __shfl_xor_sync(0xffffffff, s, o);
            float bv2 = __shfl_xor_sync(0xffffffff, bv, o);
            int   bj2 = __shfl_xor_sync(0xffffffff, bj, o);
            float mn = fmaxf(m, m2);
            s = s*__expf(m - mn) + s2*__expf(m2 - mn);
            m = mn;
            if (bv2 > bv || (bv2 == bv && bj2 < bj)) { bv = bv2; bj = bj2; }
        }
        if (lane == 0) {
            int b = w + 8*bi;
            int o = (r+1)*BATCH + b;
            g_rmax[o]  = m;
            g_marg[o]  = m + logf(s);
            g_rmaxi[o] = idx_s[bj];
        }
    }
}

// ---- per-batch verb marginals, norm, v_max, vr_maxi ----
__global__ void k_final(const float* __restrict__ vpot, const int* __restrict__ pad,
                        float* __restrict__ out_norm, float* __restrict__ out_vmax,
                        float* __restrict__ out_vrmaxi) {
    int b = blockIdx.x;
    __shared__ float ms[NR+1], xs2[NR+1];
    __shared__ int   is_[NR+1];
    __shared__ float vm_s[NV];
    __shared__ float red[256];
    int tid = threadIdx.x;
    for (int p = tid; p <= NR; p += 256) {
        ms[p]  = g_marg[p*BATCH + b];
        xs2[p] = g_rmax[p*BATCH + b];
        is_[p] = g_rmaxi[p*BATCH + b];
    }
    __syncthreads();
    for (int v = tid; v < NV; v += 256) {
        float vp = vpot[b*NV + v];
        float sm = vp, sx = vp;
        #pragma unroll
        for (int mm = 0; mm < MR; mm++) {
            int p = pad[v*MR + mm];
            sm += ms[p];
            sx += xs2[p];
            out_vrmaxi[(size_t)(b*NV + v)*MR + mm] = (float)is_[p];
        }
        vm_s[v] = sm;
        out_vmax[b*NV + v] = sx;
    }
    __syncthreads();
    float lm = -INFINITY;
    for (int v = tid; v < NV; v += 256) lm = fmaxf(lm, vm_s[v]);
    red[tid] = lm; __syncthreads();
    for (int o = 128; o > 0; o >>= 1) { if (tid < o) red[tid] = fmaxf(red[tid], red[tid+o]); __syncthreads(); }
    float gm = red[0]; __syncthreads();
    float ls = 0.f;
    for (int v = tid; v < NV; v += 256) ls += __expf(vm_s[v] - gm);
    red[tid] = ls; __syncthreads();
    for (int o = 128; o > 0; o >>= 1) { if (tid < o) red[tid] += red[tid+o]; __syncthreads(); }
    if (tid == 0) out_norm[b] = gm + logf(red[0]);
}

extern "C" void kernel_launch(void* const* d_in, const int* in_sizes, int n_in,
                              void* d_out, int out_size) {
    const float* rep = (const float*)d_in[0];
    const float* Wv  = (const float*)d_in[1];
    const float* bv  = (const float*)d_in[2];
    const float* Wr  = (const float*)d_in[3];
    const float* br  = (const float*)d_in[4];
    const float* aiw = (const float*)d_in[5];
    const float* aib = (const float*)d_in[6];
    const float* aow = (const float*)d_in[7];
    const float* aob = (const float*)d_in[8];
    const float* Wn  = (const float*)d_in[9];
    const float* bn  = (const float*)d_in[10];
    const int* rnidx = (const int*)d_in[11];
    const int* pad   = (const int*)d_in[12];
    float* out = (float*)d_out;

    k_front<<<300, 256>>>(rep, Wv, bv, Wr, br, aiw, aib, aow, aob, Wn, bn,
                          out + OFF_VPOT);                                     // 1
    k_attn<<<dim3(BATCH, NH), 768>>>(aiw, aib, 0, 0, 1);                       // 2
    k_attn<<<dim3(BATCH, NH), 768>>>(aiw, aib, 1, 1, 0);                       // 3
    k_attn<<<dim3(BATCH, NH), 768>>>(aiw, aib, 2, 0, 1);                       // 4
    k_rngemm_mma<<<dim3(91, 95), 256>>>(out + OFF_RN);                         // 5
    k_roles<<<NR, 256>>>(rnidx);                                               // 6
    k_final<<<BATCH, 256>>>(out + OFF_VPOT, pad,
                            out + OFF_NORM, out + OFF_VMAX, out + OFF_VRMAXI); // 7
    cudaMemcpyAsync(out + OFF_REP, rep, (size_t)BATCH*REPD*sizeof(float),
                    cudaMemcpyDeviceToDevice, 0);                              // 8
}